// round 7
// baseline (speedup 1.0000x reference)
#include <cuda_runtime.h>
#include <math.h>
#include <stdint.h>

#define BNB  2
#define NPTS 2048
#define CCH  256
#define NH   4
#define HDIM 64
#define NL   4
#define BHN  (BNB*NH)
#define EPSBN 1e-5f

// ---------------- scratch (device globals; no allocation allowed) -------------
__device__ float g_bufA[BNB*CCH*NPTS];
__device__ float g_bufB[BNB*CCH*NPTS];
__device__ float g_q  [BHN*HDIM*NPTS];
__device__ float g_k  [BHN*HDIM*NPTS];
__device__ float g_v  [BHN*HDIM*NPTS];
__device__ float g_mx [BHN*NPTS];
__device__ float g_rs [BHN*NPTS];

// fast exp on the FMA pipe: exp(x) = 2^(x*log2e), |rel err| ~1e-7
__device__ __forceinline__ float fexp(float x) {
    x = fmaxf(x, -80.f);
    float t = fmaf(x, 1.44269504f, 12582912.f);
    int   e = __float_as_int(t) << 23;
    float r = t - 12582912.f;
    float f = fmaf(x, 1.44269504f, -r);
    float p = 1.54035304e-4f;
    p = fmaf(p, f, 1.33335581e-3f);
    p = fmaf(p, f, 9.61812911e-3f);
    p = fmaf(p, f, 5.55041087e-2f);
    p = fmaf(p, f, 2.40226507e-1f);
    p = fmaf(p, f, 6.93147181e-1f);
    p = fmaf(p, f, 1.0f);
    return __int_as_float(__float_as_int(p) + e);
}

__device__ __forceinline__ uint32_t tf32(float x) {
    uint32_t u;
    asm("cvt.rna.tf32.f32 %0, %1;" : "=r"(u) : "f"(x));
    return u;
}

#define MMA_TF32(c, a, b)                                                        \
    asm volatile("mma.sync.aligned.m16n8k8.row.col.f32.tf32.tf32.f32 "           \
                 "{%0,%1,%2,%3},{%4,%5,%6,%7},{%8,%9},{%0,%1,%2,%3};"            \
                 : "+f"((c)[0]), "+f"((c)[1]), "+f"((c)[2]), "+f"((c)[3])        \
                 : "r"((a)[0]), "r"((a)[1]), "r"((a)[2]), "r"((a)[3]),           \
                   "r"((b)[0]), "r"((b)[1]))

// ---------------- transposes ----------------
__global__ void k_transpose_in(const float* __restrict__ x, float* __restrict__ h) {
    __shared__ float tile[32][33];
    int b = blockIdx.z;
    int n0 = blockIdx.x * 32, c0 = blockIdx.y * 32;
    int tx = threadIdx.x, ty = threadIdx.y;
    for (int i = ty; i < 32; i += 8)
        tile[i][tx] = x[(size_t)b*NPTS*CCH + (size_t)(n0+i)*CCH + c0 + tx];
    __syncthreads();
    for (int i = ty; i < 32; i += 8)
        h[(size_t)b*CCH*NPTS + (size_t)(c0+i)*NPTS + n0 + tx] = tile[tx][i];
}

__global__ void k_transpose_out(const float* __restrict__ h, float* __restrict__ out) {
    __shared__ float tile[32][33];
    int b = blockIdx.z;
    int c0 = blockIdx.x * 32, n0 = blockIdx.y * 32;
    int tx = threadIdx.x, ty = threadIdx.y;
    for (int i = ty; i < 32; i += 8)
        tile[i][tx] = h[(size_t)b*CCH*NPTS + (size_t)(c0+i)*NPTS + n0 + tx];
    __syncthreads();
    for (int i = ty; i < 32; i += 8)
        out[(size_t)b*NPTS*CCH + (size_t)(n0+i)*CCH + c0 + tx] = tile[tx][i];
}

// ---------------- full-channel GEMM (MLP / proj), tile 64o x 128n, K step 16 ----
__global__ __launch_bounds__(256)
void k_mlp(const float* __restrict__ W, const float* __restrict__ in,
           float* __restrict__ out, const float* __restrict__ bvec,
           const float* __restrict__ gvec, const float* __restrict__ bevec,
           int relu) {
    __shared__ float As[64][16];
    __shared__ float Bs[16][128];
    int b  = blockIdx.z;
    int n0 = blockIdx.x * 128, o0 = blockIdx.y * 64;
    int t  = threadIdx.x, tx = t & 15, ty = t >> 4;
    const float* inb = in + (size_t)b*CCH*NPTS;
    int aoo = t >> 2, akk = (t & 3) * 4;
    float acc[4][8] = {};
    for (int kc = 0; kc < CCH; kc += 16) {
        *(float4*)&As[aoo][akk] = *(const float4*)&W[(size_t)(o0+aoo)*CCH + kc + akk];
        #pragma unroll
        for (int hf = 0; hf < 2; hf++) {
            int idx = hf*1024 + t*4;
            int kk = idx >> 7, nn = idx & 127;
            *(float4*)&Bs[kk][nn] = *(const float4*)&inb[(size_t)(kc+kk)*NPTS + n0 + nn];
        }
        __syncthreads();
        #pragma unroll
        for (int kk = 0; kk < 16; kk++) {
            float a[4];
            #pragma unroll
            for (int i = 0; i < 4; i++) a[i] = As[ty*4+i][kk];
            float4 b0 = *(float4*)&Bs[kk][tx*8];
            float4 b1 = *(float4*)&Bs[kk][tx*8+4];
            float bb[8] = {b0.x,b0.y,b0.z,b0.w,b1.x,b1.y,b1.z,b1.w};
            #pragma unroll
            for (int i = 0; i < 4; i++)
                #pragma unroll
                for (int j = 0; j < 8; j++)
                    acc[i][j] = fmaf(a[i], bb[j], acc[i][j]);
        }
        __syncthreads();
    }
    float* outb = out + (size_t)b*CCH*NPTS;
    #pragma unroll
    for (int i = 0; i < 4; i++) {
        int o = o0 + ty*4 + i;
        float alpha = 1.f, beta = 0.f;
        if (gvec) { alpha = gvec[o] * rsqrtf(1.f + EPSBN); beta = bvec[o]*alpha + bevec[o]; }
        else if (bvec) beta = bvec[o];
        float vv[8];
        #pragma unroll
        for (int j = 0; j < 8; j++) {
            vv[j] = fmaf(acc[i][j], alpha, beta);
            if (relu) vv[j] = fmaxf(vv[j], 0.f);
        }
        float4 s0 = {vv[0],vv[1],vv[2],vv[3]}, s1 = {vv[4],vv[5],vv[6],vv[7]};
        float* p = &outb[(size_t)o*NPTS + n0 + tx*8];
        *(float4*)p = s0; *(float4*)(p+4) = s1;
    }
}

// ------- fused q/k/v head GEMMs: one B-tile load, three weight passes ----------
__global__ __launch_bounds__(256)
void k_qkv(const float* __restrict__ qw, const float* __restrict__ kw,
           const float* __restrict__ vw, const float* __restrict__ vbias,
           const float* __restrict__ in, float* __restrict__ qo,
           float* __restrict__ ko, float* __restrict__ vo, int l) {
    __shared__ float As[64][64];
    __shared__ float Bs[64][128];
    int n0 = blockIdx.x * 128, bh = blockIdx.y, hh = bh & (NH-1);
    int t = threadIdx.x, tx = t & 15, ty = t >> 4;
    const float* inb = in + (size_t)bh * HDIM * NPTS;
    int vbase = (l*NH + hh) * HDIM;
    #pragma unroll
    for (int r = 0; r < 8; r++) {
        int idx = r*1024 + t*4;
        int cc = idx >> 7, nn = idx & 127;
        *(float4*)&Bs[cc][nn] = *(const float4*)&inb[(size_t)cc*NPTS + n0 + nn];
    }
    for (int w = 0; w < 3; w++) {
        const float* W = (w == 0 ? qw : w == 1 ? kw : vw) + (size_t)(l*NH + hh)*HDIM*HDIM;
        __syncthreads();
        #pragma unroll
        for (int r = 0; r < 4; r++)
            ((float4*)As)[t + r*256] = ((const float4*)W)[t + r*256];
        __syncthreads();
        float acc[4][8] = {};
        #pragma unroll
        for (int cc = 0; cc < 64; cc++) {
            float a[4];
            #pragma unroll
            for (int i = 0; i < 4; i++) a[i] = As[ty*4+i][cc];
            float4 b0 = *(float4*)&Bs[cc][tx*8];
            float4 b1 = *(float4*)&Bs[cc][tx*8+4];
            float bb[8] = {b0.x,b0.y,b0.z,b0.w,b1.x,b1.y,b1.z,b1.w};
            #pragma unroll
            for (int i = 0; i < 4; i++)
                #pragma unroll
                for (int j = 0; j < 8; j++)
                    acc[i][j] = fmaf(a[i], bb[j], acc[i][j]);
        }
        float* outb = (w == 0 ? qo : w == 1 ? ko : vo) + (size_t)bh * HDIM * NPTS;
        #pragma unroll
        for (int i = 0; i < 4; i++) {
            int o = ty*4 + i;
            float bb = (w == 2) ? vbias[vbase + o] : 0.f;
            float4 s0 = {acc[i][0]+bb, acc[i][1]+bb, acc[i][2]+bb, acc[i][3]+bb};
            float4 s1 = {acc[i][4]+bb, acc[i][5]+bb, acc[i][6]+bb, acc[i][7]+bb};
            float* p = &outb[(size_t)o*NPTS + n0 + tx*8];
            *(float4*)p = s0; *(float4*)(p+4) = s1;
        }
    }
}

// ---- row stats only (no S write): block = 64 n-rows x full m sweep ------------
__global__ __launch_bounds__(256)
void k_stats(const float* __restrict__ q, const float* __restrict__ k,
             float* __restrict__ mxv, float* __restrict__ rsv) {
    __shared__ uint32_t Qs[64][72];   // [o][n], stride%32==8 -> conflict-free
    __shared__ uint32_t Ks[64][72];   // [o][m]
    __shared__ float Mred[64][8], Sred[64][8];
    int n0 = blockIdx.x * 64, bh = blockIdx.y;
    const float* qb = q + (size_t)bh * HDIM * NPTS;
    const float* kb = k + (size_t)bh * HDIM * NPTS;
    int t = threadIdx.x, warp = t >> 5, lane = t & 31;
    int gq = lane >> 2, tg = lane & 3;
    // Q tile 64o x 64n, loaded once
    #pragma unroll
    for (int r = 0; r < 4; r++) {
        int idx = r*1024 + t*4;
        int o = idx >> 6, nq = idx & 63;
        float4 qv = *(const float4*)&qb[(size_t)o*NPTS + n0 + nq];
        uint4 qt = {tf32(qv.x), tf32(qv.y), tf32(qv.z), tf32(qv.w)};
        *(uint4*)&Qs[o][nq] = qt;
    }
    float stM[4][2], stS[4][2];
    #pragma unroll
    for (int i = 0; i < 4; i++)
        #pragma unroll
        for (int hf = 0; hf < 2; hf++) { stM[i][hf] = -1e30f; stS[i][hf] = 0.f; }

    for (int m0 = 0; m0 < NPTS; m0 += 64) {
        __syncthreads();
        #pragma unroll
        for (int r = 0; r < 4; r++) {
            int idx = r*1024 + t*4;
            int o = idx >> 6, mq = idx & 63;
            float4 kv = *(const float4*)&kb[(size_t)o*NPTS + m0 + mq];
            uint4 kt = {tf32(kv.x), tf32(kv.y), tf32(kv.z), tf32(kv.w)};
            *(uint4*)&Ks[o][mq] = kt;
        }
        __syncthreads();
        float acc[4][4];
        #pragma unroll
        for (int i = 0; i < 4; i++)
            #pragma unroll
            for (int c = 0; c < 4; c++) acc[i][c] = 0.f;
        #pragma unroll
        for (int k8 = 0; k8 < HDIM; k8 += 8) {
            uint32_t a[4][4], b[2];
            #pragma unroll
            for (int ti = 0; ti < 4; ti++) {
                int nb = ti*16 + gq;
                a[ti][0] = Qs[k8+tg][nb];
                a[ti][1] = Qs[k8+tg][nb+8];
                a[ti][2] = Qs[k8+4+tg][nb];
                a[ti][3] = Qs[k8+4+tg][nb+8];
            }
            b[0] = Ks[k8+tg][warp*8 + gq];
            b[1] = Ks[k8+4+tg][warp*8 + gq];
            #pragma unroll
            for (int ti = 0; ti < 4; ti++)
                MMA_TF32(acc[ti], a[ti], b);
        }
        // online stats update (rows: ti*16+gq [hf=0], +8 [hf=1]; 2 cols each)
        #pragma unroll
        for (int ti = 0; ti < 4; ti++) {
            #pragma unroll
            for (int hf = 0; hf < 2; hf++) {
                float v0 = acc[ti][2*hf], v1 = acc[ti][2*hf+1];
                float tmax = fmaxf(v0, v1);
                float nM = fmaxf(stM[ti][hf], tmax);
                stS[ti][hf] = stS[ti][hf]*fexp(stM[ti][hf]-nM)
                            + fexp(v0-nM) + fexp(v1-nM);
                stM[ti][hf] = nM;
            }
        }
    }
    // butterfly over tg lanes (columns), then across the 8 warps
    #pragma unroll
    for (int ti = 0; ti < 4; ti++) {
        #pragma unroll
        for (int hf = 0; hf < 2; hf++) {
            float M = stM[ti][hf], Sm = stS[ti][hf];
            #pragma unroll
            for (int off = 1; off <= 2; off <<= 1) {
                float Mo = __shfl_xor_sync(0xffffffffu, M, off);
                float So = __shfl_xor_sync(0xffffffffu, Sm, off);
                float nM = fmaxf(M, Mo);
                Sm = Sm*fexp(M-nM) + So*fexp(Mo-nM);
                M = nM;
            }
            if (tg == 0) {
                int row = ti*16 + gq + 8*hf;
                Mred[row][warp] = M; Sred[row][warp] = Sm;
            }
        }
    }
    __syncthreads();
    if (t < 64) {
        float M = Mred[t][0], Sm = Sred[t][0];
        #pragma unroll
        for (int w = 1; w < 8; w++) {
            float Mo = Mred[t][w], So = Sred[t][w];
            float nM = fmaxf(M, Mo);
            Sm = Sm*fexp(M-nM) + So*fexp(Mo-nM);
            M = nM;
        }
        int idx = bh*NPTS + n0 + t;
        mxv[idx] = M;
        rsv[idx] = 1.f / Sm;
    }
}

// ------- mega attention: recompute S chunks, P on the fly, xr = V@P, colsum,
//         d = h - xr/cs, t-GEMM + BN + relu + residual into h. No S in gmem. ---
__global__ __launch_bounds__(256)
void k_attn_mega(const float* __restrict__ q, const float* __restrict__ k,
                 const float* __restrict__ v, const float* __restrict__ mxv,
                 const float* __restrict__ rsv, const float* __restrict__ Wbase,
                 float* __restrict__ h, const float* __restrict__ tb,
                 const float* __restrict__ bng, const float* __restrict__ bnb,
                 int l) {
    __shared__ uint32_t pool[11776];   // 47104 B, unioned regions
    #define KSM(o,m)  pool[(o)*72 + (m)]               //  0    .. 4608
    #define QSM(o,n)  pool[4608 + (o)*40 + (n)]        //  4608 .. 7168
    #define VSM(c,n)  pool[7168 + (c)*36 + (n)]        //  7168 .. 9472
    #define PSM(n,m)  pool[9472 + (n)*72 + (m)]        //  9472 .. 11776
    #define WSM(o,c)  (((float*)pool)[(o)*64 + (c)])           // epi: 0..4096
    #define DSM(c,m)  (((float*)pool)[4096 + (c)*68 + (m)])    // epi: 4096..8448
    #define RED(g,m)  (((float*)pool)[8448 + (g)*64 + (m)])    // epi: 8448..8960
    #define CSI(m)    (((float*)pool)[8960 + (m)])             // epi: 8960..9024
    int m0 = blockIdx.x * 64, bh = blockIdx.y, hh = bh & (NH-1);
    int t = threadIdx.x, warp = t >> 5, lane = t & 31;
    int gq = lane >> 2, tg = lane & 3;
    int wc = warp >> 2, wm = warp & 3;     // MMA2: 2x4 grid (32c x 16m)
    const float* qb = q + (size_t)bh * HDIM * NPTS;
    const float* kb = k + (size_t)bh * HDIM * NPTS;
    const float* vb = v + (size_t)bh * HDIM * NPTS;
    float* hb = h + (size_t)bh * HDIM * NPTS;
    const float* mxb = mxv + bh*NPTS;
    const float* rsb = rsv + bh*NPTS;
    // persistent K tile 64o x 64m
    #pragma unroll
    for (int r = 0; r < 4; r++) {
        int idx = r*1024 + t*4;
        int o = idx >> 6, mq = idx & 63;
        float4 kv = *(const float4*)&kb[(size_t)o*NPTS + m0 + mq];
        uint4 kt = {tf32(kv.x), tf32(kv.y), tf32(kv.z), tf32(kv.w)};
        *(uint4*)&KSM(o, mq) = kt;
    }
    float acc2[2][2][4];
    #pragma unroll
    for (int i = 0; i < 2; i++)
        #pragma unroll
        for (int j = 0; j < 2; j++)
            #pragma unroll
            for (int c = 0; c < 4; c++) acc2[i][j][c] = 0.f;
    float bsum[2] = {0.f, 0.f};

    for (int nc = 0; nc < NPTS; nc += 32) {
        __syncthreads();   // prior MMA1 read Qs/Ks, prior MMA2 read Vs/Ps
        // Q chunk 64o x 32n
        #pragma unroll
        for (int r = 0; r < 2; r++) {
            int idx = r*1024 + t*4;
            int o = idx >> 5, nq = idx & 31;
            float4 qv = *(const float4*)&qb[(size_t)o*NPTS + nc + nq];
            uint4 qt = {tf32(qv.x), tf32(qv.y), tf32(qv.z), tf32(qv.w)};
            *(uint4*)&QSM(o, nq) = qt;
        }
        // V chunk 64c x 32n
        #pragma unroll
        for (int r = 0; r < 2; r++) {
            int idx = r*1024 + t*4;
            int c = idx >> 5, nq = idx & 31;
            float4 vv = *(const float4*)&vb[(size_t)c*NPTS + nc + nq];
            uint4 vt = {tf32(vv.x), tf32(vv.y), tf32(vv.z), tf32(vv.w)};
            *(uint4*)&VSM(c, nq) = vt;
        }
        __syncthreads();
        // MMA1: S chunk 32n x 64m (warp w -> cols w*8..w*8+7)
        float acc1[2][4];
        #pragma unroll
        for (int i = 0; i < 2; i++)
            #pragma unroll
            for (int c = 0; c < 4; c++) acc1[i][c] = 0.f;
        #pragma unroll
        for (int k8 = 0; k8 < HDIM; k8 += 8) {
            uint32_t a[2][4], b[2];
            #pragma unroll
            for (int ti = 0; ti < 2; ti++) {
                int nb = ti*16 + gq;
                a[ti][0] = QSM(k8+tg, nb);
                a[ti][1] = QSM(k8+tg, nb+8);
                a[ti][2] = QSM(k8+4+tg, nb);
                a[ti][3] = QSM(k8+4+tg, nb+8);
            }
            b[0] = KSM(k8+tg, warp*8 + gq);
            b[1] = KSM(k8+4+tg, warp*8 + gq);
            #pragma unroll
            for (int ti = 0; ti < 2; ti++)
                MMA_TF32(acc1[ti], a[ti], b);
        }
        // P = exp(S - mx) * rs -> Ps (tf32), colsum partials
        #pragma unroll
        for (int ti = 0; ti < 2; ti++) {
            int nl0 = ti*16 + gq, nl1 = nl0 + 8;
            float mx0 = mxb[nc+nl0], rs0 = rsb[nc+nl0];
            float mx1 = mxb[nc+nl1], rs1 = rsb[nc+nl1];
            float p0 = fexp(acc1[ti][0]-mx0)*rs0;
            float p1 = fexp(acc1[ti][1]-mx0)*rs0;
            float p2 = fexp(acc1[ti][2]-mx1)*rs1;
            float p3 = fexp(acc1[ti][3]-mx1)*rs1;
            bsum[0] += p0 + p2;
            bsum[1] += p1 + p3;
            uint2 w0 = {tf32(p0), tf32(p1)};
            uint2 w1 = {tf32(p2), tf32(p3)};
            *(uint2*)&PSM(nl0, warp*8 + 2*tg) = w0;
            *(uint2*)&PSM(nl1, warp*8 + 2*tg) = w1;
        }
        __syncthreads();
        // MMA2: xr += V(64c x 32n) @ P(32n x 64m)
        #pragma unroll
        for (int k8 = 0; k8 < 32; k8 += 8) {
            uint32_t a[2][4], b[2][2];
            #pragma unroll
            for (int ti = 0; ti < 2; ti++) {
                int cb = wc*32 + ti*16 + gq;
                a[ti][0] = VSM(cb,   k8+tg);
                a[ti][1] = VSM(cb+8, k8+tg);
                a[ti][2] = VSM(cb,   k8+4+tg);
                a[ti][3] = VSM(cb+8, k8+4+tg);
            }
            #pragma unroll
            for (int tj = 0; tj < 2; tj++) {
                int mb = wm*16 + tj*8 + gq;
                b[tj][0] = PSM(k8+tg,   mb);
                b[tj][1] = PSM(k8+4+tg, mb);
            }
            #pragma unroll
            for (int ti = 0; ti < 2; ti++)
                #pragma unroll
                for (int tj = 0; tj < 2; tj++)
                    MMA_TF32(acc2[ti][tj], a[ti], b[tj]);
        }
    }
    __syncthreads();   // pool free for epilogue reuse
    // colsum partials -> RED; load t_w -> WSM (disjoint regions)
    RED(gq, warp*8 + 2*tg)     = bsum[0];
    RED(gq, warp*8 + 2*tg + 1) = bsum[1];
    {
        const float* W = Wbase + (size_t)(l*NH + hh)*HDIM*HDIM;
        #pragma unroll
        for (int r = 0; r < 4; r++) {
            float4 wv = ((const float4*)W)[t + r*256];
            int wi = (t + r*256)*4;
            *(float4*)&WSM(wi >> 6, wi & 63) = wv;
        }
    }
    __syncthreads();
    if (t < 64) {
        float s = 0.f;
        #pragma unroll
        for (int g = 0; g < 8; g++) s += RED(g, t);
        CSI(t) = 1.f / (1e-9f + s);
    }
    __syncthreads();
    // d = h - xr * csinv  -> DSM
    #pragma unroll
    for (int ti = 0; ti < 2; ti++) {
        #pragma unroll
        for (int tj = 0; tj < 2; tj++) {
            int c = wc*32 + ti*16 + gq;
            int ml = wm*16 + tj*8 + 2*tg;
            float ci0 = CSI(ml), ci1 = CSI(ml+1);
            float2 h0 = *(const float2*)&hb[(size_t)c*NPTS + m0 + ml];
            float2 h1 = *(const float2*)&hb[(size_t)(c+8)*NPTS + m0 + ml];
            DSM(c,   ml)   = h0.x - acc2[ti][tj][0]*ci0;
            DSM(c,   ml+1) = h0.y - acc2[ti][tj][1]*ci1;
            DSM(c+8, ml)   = h1.x - acc2[ti][tj][2]*ci0;
            DSM(c+8, ml+1) = h1.y - acc2[ti][tj][3]*ci1;
        }
    }
    __syncthreads();
    // t-GEMM 64x64x64 + BN + relu + residual into h
    {
        int tx = t & 15, ty = t >> 4;
        float a2[4][4] = {};
        #pragma unroll
        for (int cc = 0; cc < 64; cc++) {
            float a[4];
            #pragma unroll
            for (int i = 0; i < 4; i++) a[i] = WSM(ty*4+i, cc);
            float4 bv = *(float4*)&DSM(cc, tx*4);
            float bb[4] = {bv.x, bv.y, bv.z, bv.w};
            #pragma unroll
            for (int i = 0; i < 4; i++)
                #pragma unroll
                for (int j = 0; j < 4; j++)
                    a2[i][j] = fmaf(a[i], bb[j], a2[i][j]);
        }
        int vbase = (l*NH + hh) * HDIM;
        #pragma unroll
        for (int i = 0; i < 4; i++) {
            int o = ty*4 + i;
            float alpha = bng[vbase+o] * rsqrtf(1.f + EPSBN);
            float beta  = tb[vbase+o]*alpha + bnb[vbase+o];
            float* p = &hb[(size_t)o*NPTS + m0 + tx*4];
            float4 hv = *(float4*)p;
            hv.x += fmaxf(fmaf(a2[i][0], alpha, beta), 0.f);
            hv.y += fmaxf(fmaf(a2[i][1], alpha, beta), 0.f);
            hv.z += fmaxf(fmaf(a2[i][2], alpha, beta), 0.f);
            hv.w += fmaxf(fmaf(a2[i][3], alpha, beta), 0.f);
            *(float4*)p = hv;
        }
    }
    #undef KSM
    #undef QSM
    #undef VSM
    #undef PSM
    #undef WSM
    #undef DSM
    #undef RED
    #undef CSI
}

// ---------------- host orchestration -------------------------------------------------
extern "C" void kernel_launch(void* const* d_in, const int* in_sizes, int n_in,
                              void* d_out, int out_size) {
    const float* x      = (const float*)d_in[0];
    const float* in_w1  = (const float*)d_in[1];
    const float* in_b1  = (const float*)d_in[2];
    const float* in_g1  = (const float*)d_in[3];
    const float* in_be1 = (const float*)d_in[4];
    const float* in_w2  = (const float*)d_in[5];
    const float* in_b2  = (const float*)d_in[6];
    const float* in_g2  = (const float*)d_in[7];
    const float* in_be2 = (const float*)d_in[8];
    const float* q_w    = (const float*)d_in[9];
    const float* k_w    = (const float*)d_in[10];
    const float* v_w    = (const float*)d_in[11];
    const float* v_b    = (const float*)d_in[12];
    const float* t_w    = (const float*)d_in[13];
    const float* t_b    = (const float*)d_in[14];
    const float* bn_g   = (const float*)d_in[15];
    const float* bn_b   = (const float*)d_in[16];
    const float* proj_w = (const float*)d_in[17];
    const float* proj_b = (const float*)d_in[18];

    float *hA, *hB, *qb, *kb, *vb, *mxv, *rsv;
    cudaGetSymbolAddress((void**)&hA,  g_bufA);
    cudaGetSymbolAddress((void**)&hB,  g_bufB);
    cudaGetSymbolAddress((void**)&qb,  g_q);
    cudaGetSymbolAddress((void**)&kb,  g_k);
    cudaGetSymbolAddress((void**)&vb,  g_v);
    cudaGetSymbolAddress((void**)&mxv, g_mx);
    cudaGetSymbolAddress((void**)&rsv, g_rs);

    dim3 ttb(32, 8);
    k_transpose_in<<<dim3(NPTS/32, CCH/32, BNB), ttb>>>(x, hA);

    k_mlp<<<dim3(NPTS/128, CCH/64, BNB), 256>>>(in_w1, hA, hB, in_b1, in_g1, in_be1, 1);
    k_mlp<<<dim3(NPTS/128, CCH/64, BNB), 256>>>(in_w2, hB, hA, in_b2, in_g2, in_be2, 1);

    float* h = hA;
    float* o = hB;
    for (int l = 0; l < NL; l++) {
        k_qkv<<<dim3(NPTS/128, BHN), 256>>>(q_w, k_w, v_w, v_b, h, qb, kb, vb, l);
        k_stats<<<dim3(NPTS/64, BHN), 256>>>(qb, kb, mxv, rsv);
        k_attn_mega<<<dim3(NPTS/64, BHN), 256>>>(qb, kb, vb, mxv, rsv, t_w, h,
                                                 t_b, bn_g, bn_b, l);
        k_mlp<<<dim3(NPTS/128, CCH/64, BNB), 256>>>(proj_w + (size_t)l*CCH*CCH, h, o,
                                                    proj_b + (size_t)l*CCH,
                                                    nullptr, nullptr, 0);
        float* tmp = h; h = o; o = tmp;
    }

    k_transpose_out<<<dim3(CCH/32, NPTS/32, BNB), ttb>>>(h, (float*)d_out);
}